// round 16
// baseline (speedup 1.0000x reference)
#include <cuda_runtime.h>
#include <cstdint>

// PointerNet_30949534335591 — FINAL (terminal since R6; best sample 4.93us)
//
// Output identity (exact, rel_err = 0.0 across 12 valid rounds): the
// decoder's logits are [B, 1]; argmax over the length-1 axis is identically
// 0. The output is a constant zero [B, S] int32 tensor; the entire
// encoder/decoder LSTM stack (~110 GFLOP) is dead code w.r.t. the output.
// d_out is poisoned to 0xAA before timing, so all 512 KB must be written on
// every replay — the minimum correct write set.
//
// Proven decomposition (12 valid samples, 7 ncu profiles):
//   dur_us = 3.7 +/- 0.15 (GPU launch-to-complete; ncu 3.65-3.94, grid-size
//            independent — hardware/driver constant)
//          + 1.2-2.4      (host graph-replay jitter, bench-host property)
//          + ~0.06        (actual 512 KB store work — the only term the
//                          .cu controls, 1% of total)
// Samples: kernel node 5.79 / 4.99 / 5.92 / 5.98 / 5.98 / 5.86 / 5.02 /
// 4.93; memset node 5.06 / 5.09 / 5.89 / 6.05 — one distribution. The
// session best improved twice (4.99 -> 4.93) on byte-identical source:
// dur_us variation is host jitter, not kernel quality. No source lever
// remains (regs=16, one wave, unpredicated 16B stores, no barriers,
// minimum write set, both node types sampled).
//
// 64 CTAs x 256 threads x 2 int4 = 131072 int32 = 512 KB, exact cover.

__global__ void __launch_bounds__(256, 1)
pointer_net_zero2(int4* __restrict__ out) {
    int idx = (blockIdx.x * 256 + threadIdx.x) * 2;
    const int4 z = make_int4(0, 0, 0, 0);
    out[idx]     = z;
    out[idx + 1] = z;
}

__global__ void pointer_net_zero_generic(int* __restrict__ out, int n) {
    int idx = blockIdx.x * blockDim.x + threadIdx.x;
    if (idx < n) out[idx] = 0;
}

extern "C" void kernel_launch(void* const* d_in, const int* in_sizes, int n_in,
                              void* d_out, int out_size) {
    (void)d_in; (void)in_sizes; (void)n_in;

    uintptr_t p = reinterpret_cast<uintptr_t>(d_out);
    if (out_size == 131072 && (p & 0xF) == 0) {
        // Exact expected shape: B*S = 256*512. One wave, unpredicated stores.
        pointer_net_zero2<<<64, 256>>>(reinterpret_cast<int4*>(d_out));
    } else {
        int threads = 256;
        int blocks = (out_size + threads - 1) / threads;
        pointer_net_zero_generic<<<blocks, threads>>>(
            reinterpret_cast<int*>(d_out), out_size);
    }
}

// round 17
// speedup vs baseline: 1.0392x; 1.0392x over previous
#include <cuda_runtime.h>
#include <cstdint>

// PointerNet_30949534335591 — FINAL (terminal since R6; best sample 4.93us)
//
// Output identity (exact, rel_err = 0.0 across 13 valid rounds): the
// decoder's logits are [B, 1]; argmax over the length-1 axis is identically
// 0. The output is a constant zero [B, S] int32 tensor; the entire
// encoder/decoder LSTM stack (~110 GFLOP) is dead code w.r.t. the output.
// d_out is poisoned to 0xAA before timing, so all 512 KB must be written on
// every replay — the minimum correct write set.
//
// Proven decomposition (13 valid samples, 8 ncu profiles):
//   dur_us = 3.8 +/- 0.2 (GPU launch-to-complete; ncu 3.65-3.97, grid-size
//            independent — hardware/driver constant)
//          + 1.1-2.4     (host graph-replay jitter, bench-host property)
//          + ~0.06       (actual 512 KB store work — the only term the .cu
//                         controls, ~1% of total)
// Samples: kernel node 5.79 / 4.99 / 5.92 / 5.98 / 5.98 / 5.86 / 5.02 /
// 4.93 / 5.09; memset node 5.06 / 5.09 / 5.89 / 6.05 — one distribution.
// Best (4.93) and worst (6.05) readings came from semantically identical
// graphs: the spread is the host. Minimum node count, minimum write set,
// cheapest-sampled node type, regs=16, one wave, unpredicated 16B stores.
// No experiment remains whose outcome the model doesn't already predict.
//
// 64 CTAs x 256 threads x 2 int4 = 131072 int32 = 512 KB, exact cover.

__global__ void __launch_bounds__(256, 1)
pointer_net_zero2(int4* __restrict__ out) {
    int idx = (blockIdx.x * 256 + threadIdx.x) * 2;
    const int4 z = make_int4(0, 0, 0, 0);
    out[idx]     = z;
    out[idx + 1] = z;
}

__global__ void pointer_net_zero_generic(int* __restrict__ out, int n) {
    int idx = blockIdx.x * blockDim.x + threadIdx.x;
    if (idx < n) out[idx] = 0;
}

extern "C" void kernel_launch(void* const* d_in, const int* in_sizes, int n_in,
                              void* d_out, int out_size) {
    (void)d_in; (void)in_sizes; (void)n_in;

    uintptr_t p = reinterpret_cast<uintptr_t>(d_out);
    if (out_size == 131072 && (p & 0xF) == 0) {
        // Exact expected shape: B*S = 256*512. One wave, unpredicated stores.
        pointer_net_zero2<<<64, 256>>>(reinterpret_cast<int4*>(d_out));
    } else {
        int threads = 256;
        int blocks = (out_size + threads - 1) / threads;
        pointer_net_zero_generic<<<blocks, threads>>>(
            reinterpret_cast<int*>(d_out), out_size);
    }
}